// round 4
// baseline (speedup 1.0000x reference)
#include <cuda_runtime.h>
#include <cuda_bf16.h>
#include <math.h>
#include <stdint.h>

// ---------------- problem constants ----------------
#define NN      100000      // nodes
#define NPAD    100096      // padded to 782*128
#define EE      1600000     // edges
#define GG      4096        // graphs
#define NLAYER  4           // 1 input conv + 3 blocks

// ---------------- static scratch (no allocations allowed) ----------------
__device__ float g_h0[(size_t)NPAD * 128];      // ping
__device__ float g_h1[(size_t)NPAD * 128];      // pong
__device__ float g_qkvs[(size_t)NPAD * 512];    // [q|k|v|s] per node
__device__ int   g_deg[NN];
__device__ int   g_rowptr[NN + 1];
__device__ int   g_cursor[NN];
__device__ int   g_src[EE];                     // src node per CSR slot (sorted by dst)
__device__ float g_pool[GG * 128];
__device__ float g_cnt[GG];
// split-bf16 weights: [layer][hi|lo][512 n][128 k] halves  (n-major, k-contiguous)
__device__ __nv_bfloat16 g_wtb[(size_t)NLAYER * 2 * 512 * 128];

struct AllW {
    const float* W[16];   // [layer*4 + {q,k,v,s}] each 128x128 row-major (in,out)
    const float* b[16];
};

// ---------------- utility kernels ----------------
__global__ void k_zero() {
    int i = blockIdx.x * blockDim.x + threadIdx.x;
    if (i < NN) g_deg[i] = 0;
    if (i < GG * 128) g_pool[i] = 0.f;
    if (i < GG) g_cnt[i] = 0.f;
}

__global__ void k_count(const int* __restrict__ ei) {
    int e = blockIdx.x * blockDim.x + threadIdx.x;
    if (e < EE) atomicAdd(&g_deg[ei[EE + e]], 1);
}

__global__ void k_scan() {
    __shared__ int ssum[1024];
    int t = threadIdx.x;
    const int per = (NN + 1023) >> 10;
    int lo = t * per;
    int hi = lo + per; if (hi > NN) hi = NN;
    if (lo > NN) lo = NN;
    int s = 0;
    for (int i = lo; i < hi; ++i) s += g_deg[i];
    ssum[t] = s;
    __syncthreads();
    for (int off = 1; off < 1024; off <<= 1) {
        int v = (t >= off) ? ssum[t - off] : 0;
        __syncthreads();
        ssum[t] += v;
        __syncthreads();
    }
    int run = (t == 0) ? 0 : ssum[t - 1];
    for (int i = lo; i < hi; ++i) {
        g_rowptr[i] = run;
        g_cursor[i] = run;
        run += g_deg[i];
    }
    if (t == 1023) g_rowptr[NN] = run;
}

__global__ void k_scatter(const int* __restrict__ ei) {
    int e = blockIdx.x * blockDim.x + threadIdx.x;
    if (e < EE) {
        int s = ei[e];
        int d = ei[EE + e];
        int slot = atomicAdd(&g_cursor[d], 1);
        g_src[slot] = s;
    }
}

// ---------------- weight prepass: transpose + split-bf16 ----------------
// Output layout: g_wtb[((l*2 + hilo)*512 + n)*128 + k]
__global__ void k_prepw(AllW aw) {
    int e = blockIdx.x * blockDim.x + threadIdx.x;
    if (e >= NLAYER * 512 * 128) return;
    int l = e >> 16;         // 512*128 = 65536 per layer
    int r = e & 65535;
    int n = r >> 7;          // output col 0..511
    int k = r & 127;         // input dim
    const float* W = aw.W[l * 4 + (n >> 7)];
    float v = W[k * 128 + (n & 127)];
    __nv_bfloat16 hi = __float2bfloat16(v);
    float resid = v - __bfloat162float(hi);
    __nv_bfloat16 lo = __float2bfloat16(resid);
    g_wtb[((size_t)(l * 2 + 0) * 512 + n) * 128 + k] = hi;
    g_wtb[((size_t)(l * 2 + 1) * 512 + n) * 128 + k] = lo;
}

// ---------------- mma.sync helper ----------------
__device__ __forceinline__ void mma16816(float* d, const uint32_t* a, const uint32_t* b) {
    asm volatile(
        "mma.sync.aligned.m16n8k16.row.col.f32.bf16.bf16.f32 "
        "{%0,%1,%2,%3}, {%4,%5,%6,%7}, {%8,%9}, {%0,%1,%2,%3};"
        : "+f"(d[0]), "+f"(d[1]), "+f"(d[2]), "+f"(d[3])
        : "r"(a[0]), "r"(a[1]), "r"(a[2]), "r"(a[3]), "r"(b[0]), "r"(b[1]));
}

// ---------------- tensor-core QKVS GEMM via mma.sync (split-bf16) ----------------
// C[NPAD,512] = A[NPAD,128] @ Wconcat + b.  D = Ah*Bh + Ah*Bl + Al*Bh, fp32 accum.
// One CTA per 128-row tile; A staged ONCE (full K) in smem; loop 4 slabs x 4 k-chunks
// streaming B. 8 warps, warp tile 64x32.
#define SASTR 136   // A smem row stride in halves
#define SBSTR 40    // B smem row stride in halves
#define SM_A_BYTES (2 * 128 * SASTR * 2)          // 69632
#define SM_B_OFF   SM_A_BYTES
#define SM_B_BYTES (2 * 128 * SBSTR * 2)          // 20480
#define SM_BIAS_OFF (SM_B_OFF + SM_B_BYTES)       // 90112
#define SM_TOTAL   (SM_BIAS_OFF + 512 * 4)        // 92160

__global__ void __launch_bounds__(256, 2) k_gemm_mma(AllW aw, int l, const float* __restrict__ A) {
    extern __shared__ char sm[];
    ushort (*sA)[128][SASTR] = (ushort (*)[128][SASTR])sm;
    ushort (*sB)[128][SBSTR] = (ushort (*)[128][SBSTR])(sm + SM_B_OFF);
    float* bias_s = (float*)(sm + SM_BIAS_OFF);

    const int tid = threadIdx.x;
    const int wid = tid >> 5, lane = tid & 31;
    const int g = lane >> 2, t2 = (lane & 3) * 2;
    const int warpRow = wid & 1, warpCol = wid >> 1;
    const int rowBase = blockIdx.x * 128;

    for (int i = tid; i < 512; i += 256)
        bias_s[i] = aw.b[l * 4 + (i >> 7)][i & 127];

    // stage full A tile 128x128 (fp32 -> split bf16), guarded against NN
#pragma unroll
    for (int it = 0; it < 16; ++it) {
        int idx = tid + it * 256;          // 0..4095 float4s
        int row = idx >> 5, c4 = idx & 31;
        int grow = rowBase + row;
        float4 v = make_float4(0.f, 0.f, 0.f, 0.f);
        if (grow < NN)
            v = *reinterpret_cast<const float4*>(A + (size_t)grow * 128 + c4 * 4);
        __nv_bfloat16 h0 = __float2bfloat16(v.x), h1 = __float2bfloat16(v.y);
        __nv_bfloat16 h2 = __float2bfloat16(v.z), h3 = __float2bfloat16(v.w);
        __nv_bfloat16 l0 = __float2bfloat16(v.x - __bfloat162float(h0));
        __nv_bfloat16 l1 = __float2bfloat16(v.y - __bfloat162float(h1));
        __nv_bfloat16 l2 = __float2bfloat16(v.z - __bfloat162float(h2));
        __nv_bfloat16 l3 = __float2bfloat16(v.w - __bfloat162float(h3));
        uint2 hp = make_uint2(
            (uint32_t)__bfloat16_as_ushort(h0) | ((uint32_t)__bfloat16_as_ushort(h1) << 16),
            (uint32_t)__bfloat16_as_ushort(h2) | ((uint32_t)__bfloat16_as_ushort(h3) << 16));
        uint2 lp = make_uint2(
            (uint32_t)__bfloat16_as_ushort(l0) | ((uint32_t)__bfloat16_as_ushort(l1) << 16),
            (uint32_t)__bfloat16_as_ushort(l2) | ((uint32_t)__bfloat16_as_ushort(l3) << 16));
        *reinterpret_cast<uint2*>(&sA[0][row][c4 * 4]) = hp;
        *reinterpret_cast<uint2*>(&sA[1][row][c4 * 4]) = lp;
    }
    __syncthreads();

    for (int slab = 0; slab < 4; ++slab) {
        const __nv_bfloat16* __restrict__ wtH = g_wtb + ((size_t)(l * 2 + 0) * 512 + slab * 128) * 128;
        const __nv_bfloat16* __restrict__ wtL = g_wtb + ((size_t)(l * 2 + 1) * 512 + slab * 128) * 128;

        float acc[4][4][4];
#pragma unroll
        for (int mt = 0; mt < 4; ++mt)
#pragma unroll
            for (int nt = 0; nt < 4; ++nt)
#pragma unroll
                for (int j = 0; j < 4; ++j) acc[mt][nt][j] = 0.f;

        for (int kc = 0; kc < 4; ++kc) {
            const int k0 = kc * 32;
            // stage B chunk: 128 n x 32 k, hi+lo
#pragma unroll
            for (int it = 0; it < 8; ++it) {
                int idx = tid + it * 256;       // 0..2047
                int h = idx >> 10;
                int r = idx & 1023;
                int n = r >> 3, q = r & 7;
                const __nv_bfloat16* w = h ? wtL : wtH;
                uint2 v = *reinterpret_cast<const uint2*>(w + (size_t)n * 128 + k0 + q * 4);
                *reinterpret_cast<uint2*>(&sB[h][n][q * 4]) = v;
            }
            __syncthreads();

#pragma unroll
            for (int ks = 0; ks < 2; ++ks) {
                const int ka = k0 + ks * 16;    // sA k offset
                const int kb = ks * 16;         // sB k offset
                uint32_t ah[4][4], al[4][4];
#pragma unroll
                for (int mt = 0; mt < 4; ++mt) {
                    int r0 = warpRow * 64 + mt * 16 + g;
                    ah[mt][0] = *reinterpret_cast<const uint32_t*>(&sA[0][r0][ka + t2]);
                    ah[mt][1] = *reinterpret_cast<const uint32_t*>(&sA[0][r0 + 8][ka + t2]);
                    ah[mt][2] = *reinterpret_cast<const uint32_t*>(&sA[0][r0][ka + t2 + 8]);
                    ah[mt][3] = *reinterpret_cast<const uint32_t*>(&sA[0][r0 + 8][ka + t2 + 8]);
                    al[mt][0] = *reinterpret_cast<const uint32_t*>(&sA[1][r0][ka + t2]);
                    al[mt][1] = *reinterpret_cast<const uint32_t*>(&sA[1][r0 + 8][ka + t2]);
                    al[mt][2] = *reinterpret_cast<const uint32_t*>(&sA[1][r0][ka + t2 + 8]);
                    al[mt][3] = *reinterpret_cast<const uint32_t*>(&sA[1][r0 + 8][ka + t2 + 8]);
                }
#pragma unroll
                for (int nt = 0; nt < 4; ++nt) {
                    int n0 = warpCol * 32 + nt * 8 + g;
                    uint32_t bh[2], bl[2];
                    bh[0] = *reinterpret_cast<const uint32_t*>(&sB[0][n0][kb + t2]);
                    bh[1] = *reinterpret_cast<const uint32_t*>(&sB[0][n0][kb + t2 + 8]);
                    bl[0] = *reinterpret_cast<const uint32_t*>(&sB[1][n0][kb + t2]);
                    bl[1] = *reinterpret_cast<const uint32_t*>(&sB[1][n0][kb + t2 + 8]);
#pragma unroll
                    for (int mt = 0; mt < 4; ++mt) {
                        mma16816(acc[mt][nt], ah[mt], bh);
                        mma16816(acc[mt][nt], ah[mt], bl);
                        mma16816(acc[mt][nt], al[mt], bh);
                    }
                }
            }
            __syncthreads();
        }

        // epilogue: bias add + store this slab
#pragma unroll
        for (int mt = 0; mt < 4; ++mt) {
#pragma unroll
            for (int nt = 0; nt < 4; ++nt) {
                int lc = warpCol * 32 + nt * 8 + t2;
                int r0 = rowBase + warpRow * 64 + mt * 16 + g;
                float2 b2 = make_float2(bias_s[slab * 128 + lc], bias_s[slab * 128 + lc + 1]);
                float* p0 = g_qkvs + (size_t)r0 * 512 + slab * 128 + lc;
                float* p1 = g_qkvs + (size_t)(r0 + 8) * 512 + slab * 128 + lc;
                *reinterpret_cast<float2*>(p0) = make_float2(acc[mt][nt][0] + b2.x, acc[mt][nt][1] + b2.y);
                *reinterpret_cast<float2*>(p1) = make_float2(acc[mt][nt][2] + b2.x, acc[mt][nt][3] + b2.y);
            }
        }
    }
}

// ---------------- attention + beta gate + relu: one warp per dst node ----------------
// Unroll-2: two independent online-softmax accumulators, merged at the end.
__global__ void __launch_bounds__(256) k_attn(const float* __restrict__ Wbeta, int cur) {
    const int warp = blockIdx.x * 8 + (threadIdx.x >> 5);
    if (warp >= NN) return;
    const int lane = threadIdx.x & 31;
    const float* __restrict__ qkvs = g_qkvs;
    float* __restrict__ hout = cur ? g_h0 : g_h1;   // write the other buffer

    const size_t base = (size_t)warp * 512;
    const float4 qv = *reinterpret_cast<const float4*>(qkvs + base + lane * 4);

    const int s0 = g_rowptr[warp];
    const int s1 = g_rowptr[warp + 1];

    float mh0 = -INFINITY, d0 = 0.f;
    float4 a0 = make_float4(0.f, 0.f, 0.f, 0.f);
    float mh1 = -INFINITY, d1 = 0.f;
    float4 a1 = make_float4(0.f, 0.f, 0.f, 0.f);

    int j = s0;
    for (; j + 1 < s1; j += 2) {
        int sa = __ldg(&g_src[j]);
        int sb = __ldg(&g_src[j + 1]);
        const float* kpa = qkvs + (size_t)sa * 512;
        const float* kpb = qkvs + (size_t)sb * 512;
        float4 ka = *reinterpret_cast<const float4*>(kpa + 128 + lane * 4);
        float4 kb = *reinterpret_cast<const float4*>(kpb + 128 + lane * 4);
        float4 va = *reinterpret_cast<const float4*>(kpa + 256 + lane * 4);
        float4 vb = *reinterpret_cast<const float4*>(kpb + 256 + lane * 4);
        float pa = qv.x * ka.x + qv.y * ka.y + qv.z * ka.z + qv.w * ka.w;
        float pb = qv.x * kb.x + qv.y * kb.y + qv.z * kb.z + qv.w * kb.w;
        pa += __shfl_xor_sync(0xffffffffu, pa, 1);
        pb += __shfl_xor_sync(0xffffffffu, pb, 1);
        pa += __shfl_xor_sync(0xffffffffu, pa, 2);
        pb += __shfl_xor_sync(0xffffffffu, pb, 2);
        pa += __shfl_xor_sync(0xffffffffu, pa, 4);
        pb += __shfl_xor_sync(0xffffffffu, pb, 4);
        float alA = pa * 0.17677669529663687f;   // 1/sqrt(32)
        float alB = pb * 0.17677669529663687f;
        float mn0 = fmaxf(mh0, alA);
        float mn1 = fmaxf(mh1, alB);
        float sc0 = __expf(mh0 - mn0);
        float sc1 = __expf(mh1 - mn1);
        float e0 = __expf(alA - mn0);
        float e1 = __expf(alB - mn1);
        d0 = d0 * sc0 + e0;
        d1 = d1 * sc1 + e1;
        a0.x = a0.x * sc0 + e0 * va.x;  a1.x = a1.x * sc1 + e1 * vb.x;
        a0.y = a0.y * sc0 + e0 * va.y;  a1.y = a1.y * sc1 + e1 * vb.y;
        a0.z = a0.z * sc0 + e0 * va.z;  a1.z = a1.z * sc1 + e1 * vb.z;
        a0.w = a0.w * sc0 + e0 * va.w;  a1.w = a1.w * sc1 + e1 * vb.w;
        mh0 = mn0;
        mh1 = mn1;
    }
    if (j < s1) {
        int sa = __ldg(&g_src[j]);
        const float* kpa = qkvs + (size_t)sa * 512;
        float4 ka = *reinterpret_cast<const float4*>(kpa + 128 + lane * 4);
        float4 va = *reinterpret_cast<const float4*>(kpa + 256 + lane * 4);
        float pa = qv.x * ka.x + qv.y * ka.y + qv.z * ka.z + qv.w * ka.w;
        pa += __shfl_xor_sync(0xffffffffu, pa, 1);
        pa += __shfl_xor_sync(0xffffffffu, pa, 2);
        pa += __shfl_xor_sync(0xffffffffu, pa, 4);
        float alA = pa * 0.17677669529663687f;
        float mn0 = fmaxf(mh0, alA);
        float sc0 = __expf(mh0 - mn0);
        float e0 = __expf(alA - mn0);
        d0 = d0 * sc0 + e0;
        a0.x = a0.x * sc0 + e0 * va.x;
        a0.y = a0.y * sc0 + e0 * va.y;
        a0.z = a0.z * sc0 + e0 * va.z;
        a0.w = a0.w * sc0 + e0 * va.w;
        mh0 = mn0;
    }

    // merge the two accumulators (NaN-safe when either/both are empty)
    float m = fmaxf(mh0, mh1);
    float s0f = (mh0 == m) ? 1.f : __expf(mh0 - m);
    float s1f = (mh1 == m) ? 1.f : __expf(mh1 - m);
    if (mh0 == -INFINITY) s0f = (mh1 == -INFINITY) ? 1.f : 0.f;
    if (mh1 == -INFINITY) s1f = 0.f;
    float denom = d0 * s0f + d1 * s1f;
    float4 acc;
    acc.x = a0.x * s0f + a1.x * s1f;
    acc.y = a0.y * s0f + a1.y * s1f;
    acc.z = a0.z * s0f + a1.z * s1f;
    acc.w = a0.w * s0f + a1.w * s1f;

    float inv = 1.f / (denom + 1e-16f);
    float4 o = make_float4(acc.x * inv, acc.y * inv, acc.z * inv, acc.w * inv);
    float4 xr = *reinterpret_cast<const float4*>(qkvs + base + 384 + lane * 4);

    const int c = lane * 4;
    float bs = o.x * Wbeta[c] + o.y * Wbeta[c + 1] + o.z * Wbeta[c + 2] + o.w * Wbeta[c + 3]
             + xr.x * Wbeta[128 + c] + xr.y * Wbeta[128 + c + 1] + xr.z * Wbeta[128 + c + 2] + xr.w * Wbeta[128 + c + 3]
             + (o.x - xr.x) * Wbeta[256 + c] + (o.y - xr.y) * Wbeta[256 + c + 1]
             + (o.z - xr.z) * Wbeta[256 + c + 2] + (o.w - xr.w) * Wbeta[256 + c + 3];
#pragma unroll
    for (int off = 16; off; off >>= 1) bs += __shfl_xor_sync(0xffffffffu, bs, off);
    float beta = 1.f / (1.f + __expf(-bs));

    float4 r;
    r.x = fmaxf(beta * xr.x + (1.f - beta) * o.x, 0.f);
    r.y = fmaxf(beta * xr.y + (1.f - beta) * o.y, 0.f);
    r.z = fmaxf(beta * xr.z + (1.f - beta) * o.z, 0.f);
    r.w = fmaxf(beta * xr.w + (1.f - beta) * o.w, 0.f);
    *reinterpret_cast<float4*>(hout + (size_t)warp * 128 + c) = r;
}

// ---------------- mean pool (atomic) ----------------
__global__ void k_pool(const int* __restrict__ batch, int cur) {
    int idx = blockIdx.x * blockDim.x + threadIdx.x;  // over NN*32 float4 chunks
    if (idx >= NN * 32) return;
    int n = idx >> 5;
    int c4 = (idx & 31) * 4;
    const float* __restrict__ h = cur ? g_h1 : g_h0;
    int b = batch[n];
    float4 v = *reinterpret_cast<const float4*>(h + (size_t)n * 128 + c4);
    atomicAdd(&g_pool[b * 128 + c4 + 0], v.x);
    atomicAdd(&g_pool[b * 128 + c4 + 1], v.y);
    atomicAdd(&g_pool[b * 128 + c4 + 2], v.z);
    atomicAdd(&g_pool[b * 128 + c4 + 3], v.w);
    if (c4 == 0) atomicAdd(&g_cnt[b], 1.f);
}

// ---------------- per-graph MLP head ----------------
__global__ void __launch_bounds__(128) k_mlp(
    const float* __restrict__ W1, const float* __restrict__ b1,
    const float* __restrict__ W2, const float* __restrict__ b2,
    const float* __restrict__ W3, const float* __restrict__ b3,
    float* __restrict__ out)
{
    int b = blockIdx.x;
    int t = threadIdx.x;
    __shared__ float sg[128];
    __shared__ float h1[64];
    __shared__ float h2[32];
    float cnt = fmaxf(g_cnt[b], 1.f);
    sg[t] = g_pool[b * 128 + t] / cnt;
    __syncthreads();
    if (t < 64) {
        float a = b1[t];
#pragma unroll 4
        for (int i = 0; i < 128; ++i) a = fmaf(sg[i], W1[i * 64 + t], a);
        h1[t] = fmaxf(a, 0.f);
    }
    __syncthreads();
    if (t < 32) {
        float a = b2[t];
#pragma unroll 4
        for (int i = 0; i < 64; ++i) a = fmaf(h1[i], W2[i * 32 + t], a);
        h2[t] = fmaxf(a, 0.f);
    }
    __syncthreads();
    if (t == 0) {
        float a = b3[0];
#pragma unroll
        for (int i = 0; i < 32; ++i) a = fmaf(h2[i], W3[i], a);
        out[b] = 1.f / (1.f + expf(-a));
    }
}

// ---------------- launch ----------------
extern "C" void kernel_launch(void* const* d_in, const int* in_sizes, int n_in,
                              void* d_out, int out_size) {
    (void)in_sizes; (void)n_in;
    const float* x      = (const float*)d_in[0];
    const int*   ei     = (const int*)d_in[1];
    const int*   batch  = (const int*)d_in[2];

    AllW aw;
    // input conv
    aw.W[0] = (const float*)d_in[3];  aw.b[0] = (const float*)d_in[4];
    aw.W[1] = (const float*)d_in[5];  aw.b[1] = (const float*)d_in[6];
    aw.W[2] = (const float*)d_in[7];  aw.b[2] = (const float*)d_in[8];
    aw.W[3] = (const float*)d_in[9];  aw.b[3] = (const float*)d_in[10];
    const float* wbeta[NLAYER];
    wbeta[0] = (const float*)d_in[11];
    const float* bWq = (const float*)d_in[12]; const float* bbq = (const float*)d_in[13];
    const float* bWk = (const float*)d_in[14]; const float* bbk = (const float*)d_in[15];
    const float* bWv = (const float*)d_in[16]; const float* bbv = (const float*)d_in[17];
    const float* bWs = (const float*)d_in[18]; const float* bbs = (const float*)d_in[19];
    const float* bWb = (const float*)d_in[20];
    for (int l = 0; l < 3; ++l) {
        aw.W[(l + 1) * 4 + 0] = bWq + (size_t)l * 128 * 128;  aw.b[(l + 1) * 4 + 0] = bbq + l * 128;
        aw.W[(l + 1) * 4 + 1] = bWk + (size_t)l * 128 * 128;  aw.b[(l + 1) * 4 + 1] = bbk + l * 128;
        aw.W[(l + 1) * 4 + 2] = bWv + (size_t)l * 128 * 128;  aw.b[(l + 1) * 4 + 2] = bbv + l * 128;
        aw.W[(l + 1) * 4 + 3] = bWs + (size_t)l * 128 * 128;  aw.b[(l + 1) * 4 + 3] = bbs + l * 128;
        wbeta[l + 1] = bWb + l * 384;
    }
    const float* W1 = (const float*)d_in[21]; const float* b1 = (const float*)d_in[22];
    const float* W2 = (const float*)d_in[23]; const float* b2 = (const float*)d_in[24];
    const float* W3 = (const float*)d_in[25]; const float* b3 = (const float*)d_in[26];
    float* out = (float*)d_out;
    (void)out_size;

    cudaFuncSetAttribute(k_gemm_mma, cudaFuncAttributeMaxDynamicSharedMemorySize, SM_TOTAL);

    // --- per-launch setup: zero accumulators, build CSR by dst, prep weights ---
    {
        int zn = GG * 128;
        k_zero<<<(zn + 255) / 256, 256>>>();
        k_count<<<(EE + 255) / 256, 256>>>(ei);
        k_scan<<<1, 1024>>>();
        k_scatter<<<(EE + 255) / 256, 256>>>(ei);
        k_prepw<<<(NLAYER * 512 * 128 + 255) / 256, 256>>>(aw);
    }

    // --- 4 transformer conv layers ---
    // GEMM l reads: l0 -> x, then the buffer attn(l-1) wrote.
    // attn(cur): cur=0 writes g_h1, cur=1 writes g_h0.
    const float* Aptr[NLAYER] = { x, g_h1, g_h0, g_h1 };
    int cur = 0;
    for (int l = 0; l < NLAYER; ++l) {
        k_gemm_mma<<<NPAD / 128, 256, SM_TOTAL>>>(aw, l, Aptr[l]);
        k_attn<<<(NN + 7) / 8, 256>>>(wbeta[l], cur);
        cur ^= 1;
    }

    // --- pool + MLP head ---
    k_pool<<<(NN * 32 + 255) / 256, 256>>>(batch, cur);
    k_mlp<<<GG, 128>>>(W1, b1, W2, b2, W3, b3, out);
}